// round 1
// baseline (speedup 1.0000x reference)
#include <cuda_runtime.h>
#include <math.h>

#define TGT   2048
#define NBSZ  2
#define EMB   1024
#define NH    16
#define HD    64
#define NBH   (NBSZ*NH)      // 32
#define MROWS (TGT*NBSZ)     // 4096

// Scratch (device globals: allocation-free rule)
static __device__ float g_Q  [(size_t)NBH*TGT*HD];   // [bh][t][d], pre-scaled
static __device__ float g_K  [(size_t)NBH*TGT*HD];   // [bh][t][d]
static __device__ float g_Vt [(size_t)NBH*HD*TGT];   // [bh][d][t]
static __device__ float g_P  [(size_t)NBH*TGT*TGT];  // logits -> probs (536 MB)
static __device__ float g_attn[(size_t)MROWS*EMB];   // pre-out-proj, [t*B+b][e]

// ---------------------------------------------------------------------------
// Generic tiled SGEMM: C[M,N] = A[M,K] * B[N,K]^T (both operands K-major).
// MODE 0: A=query, B=in_proj_w, +bias, scatter to Q/K/Vt (Q scaled)
// MODE 1: per-z (bh): A=g_Q, B=g_K -> g_P (raw logits)
// MODE 2: per-z (bh): A=g_P, B=g_Vt -> g_attn (reordered)
// MODE 3: A=g_attn, B=out_w, +bias -> d_out (attn part)
// ---------------------------------------------------------------------------
template<int BM,int BN,int TM,int TN,int MODE>
__global__ __launch_bounds__(256)
void gemm_k(const float* __restrict__ Ag,
            const float* __restrict__ Bg,
            float* __restrict__ Cg,
            const float* __restrict__ biasg,
            int Kdim)
{
    constexpr int BK = 8;
    const int tid = threadIdx.x;
    const int bx = blockIdx.x, by = blockIdx.y, z = blockIdx.z;
    const int bm = by*BM, bn = bx*BN;

    const float* A;
    const float* B;
    if (MODE == 1)      { A = g_Q + (size_t)z*TGT*HD;  B = g_K  + (size_t)z*TGT*HD;  }
    else if (MODE == 2) { A = g_P + (size_t)z*TGT*TGT; B = g_Vt + (size_t)z*HD*TGT;  }
    else if (MODE == 3) { A = g_attn;                  B = Bg;                        }
    else                { A = Ag;                      B = Bg;                        }

    __shared__ float As[BK][BM+4];
    __shared__ float Bs[BK][BN+4];

    const int tx = tid & 15;      // n direction (16)
    const int ty = tid >> 4;      // m direction (16)

    float acc[TM][TN];
    #pragma unroll
    for (int i=0;i<TM;i++)
        #pragma unroll
        for (int j=0;j<TN;j++) acc[i][j] = 0.f;

    constexpr int FB = BN*BK/4;   // float4 loads for B tile
    const int ar = tid >> 1;             // 0..127
    const int ac = (tid & 1) * 4;        // 0 or 4
    const int br = tid >> 1;
    const int bc = (tid & 1) * 4;

    for (int k0 = 0; k0 < Kdim; k0 += BK) {
        float4 av = *(const float4*)(A + (size_t)(bm+ar)*Kdim + k0 + ac);
        As[ac+0][ar]=av.x; As[ac+1][ar]=av.y; As[ac+2][ar]=av.z; As[ac+3][ar]=av.w;
        if (tid < FB) {
            float4 bv = *(const float4*)(B + (size_t)(bn+br)*Kdim + k0 + bc);
            Bs[bc+0][br]=bv.x; Bs[bc+1][br]=bv.y; Bs[bc+2][br]=bv.z; Bs[bc+3][br]=bv.w;
        }
        __syncthreads();
        #pragma unroll
        for (int kk=0; kk<BK; kk++) {
            float ra[TM], rb[TN];
            #pragma unroll
            for (int i=0;i<TM;i++) ra[i] = As[kk][ty*TM+i];
            #pragma unroll
            for (int j=0;j<TN;j++) rb[j] = Bs[kk][tx*TN+j];
            #pragma unroll
            for (int i=0;i<TM;i++)
                #pragma unroll
                for (int j=0;j<TN;j++)
                    acc[i][j] = fmaf(ra[i], rb[j], acc[i][j]);
        }
        __syncthreads();
    }

    if (MODE == 0) {
        #pragma unroll
        for (int i=0;i<TM;i++) {
            const int m = bm + ty*TM + i;
            const int t = m >> 1, b = m & 1;      // m = t*BSZ + b
            #pragma unroll
            for (int j=0;j<TN;j++) {
                const int n = bn + tx*TN + j;
                float val = acc[i][j] + biasg[n];
                const int which = n >> 10;
                const int e = n & 1023;
                const int h = e >> 6, d = e & 63;
                const int bh = b*NH + h;
                if (which == 0)      g_Q[((size_t)bh*TGT + t)*HD + d] = val * 0.125f; // HD^-0.5
                else if (which == 1) g_K[((size_t)bh*TGT + t)*HD + d] = val;
                else                 g_Vt[((size_t)bh*HD + d)*TGT + t] = val;
            }
        }
    } else if (MODE == 1) {
        float* C = g_P + (size_t)z*TGT*TGT;
        #pragma unroll
        for (int i=0;i<TM;i++) {
            const size_t rowoff = (size_t)(bm + ty*TM + i)*TGT + bn + tx*TN;
            #pragma unroll
            for (int j4=0;j4<TN/4;j4++) {
                float4 v = make_float4(acc[i][j4*4+0], acc[i][j4*4+1],
                                       acc[i][j4*4+2], acc[i][j4*4+3]);
                *(float4*)(C + rowoff + j4*4) = v;
            }
        }
    } else if (MODE == 2) {
        const int b = z >> 4, h = z & 15;
        #pragma unroll
        for (int i=0;i<TM;i++) {
            const int q = bm + ty*TM + i;
            const size_t row = (size_t)(q*NBSZ + b)*EMB + h*HD;
            #pragma unroll
            for (int j=0;j<TN;j++)
                g_attn[row + bn + tx*TN + j] = acc[i][j];
        }
    } else { // MODE 3
        #pragma unroll
        for (int i=0;i<TM;i++) {
            const int m = bm + ty*TM + i;
            #pragma unroll
            for (int j=0;j<TN;j++) {
                const int n = bn + tx*TN + j;
                Cg[(size_t)m*EMB + n] = acc[i][j] + biasg[n];
            }
        }
    }
}

// FFMA-only exp (avoids MUFU bottleneck at 134M exps). Input <= 0 after max-sub.
__device__ __forceinline__ float fast_exp(float x)
{
    float y = x * 1.4426950408889634f;        // x * log2(e)
    float n = rintf(y);
    float t = y - n;                          // |t| <= 0.5
    float p =            1.33336498e-3f;      // ln2^5/120
    p = fmaf(p, t, 9.61812910e-3f);           // ln2^4/24
    p = fmaf(p, t, 5.55041087e-2f);           // ln2^3/6
    p = fmaf(p, t, 2.40226507e-1f);           // ln2^2/2
    p = fmaf(p, t, 6.93147182e-1f);           // ln2
    p = fmaf(p, t, 1.0f);
    int e = (int)n;
    e = max(-126, min(126, e));
    return p * __int_as_float((e + 127) << 23);
}

// Row softmax in-place on g_P + head-mean -> avg output. Block per (q, b).
__global__ __launch_bounds__(256)
void softmax_avg_k(float* __restrict__ avg_out)
{
    const int q = blockIdx.x, b = blockIdx.y;
    const int tid = threadIdx.x;
    __shared__ float s_avg[TGT];
    __shared__ float sred[8];

    #pragma unroll
    for (int r=0;r<TGT/256;r++) s_avg[tid + r*256] = 0.f;

    for (int h=0; h<NH; h++) {
        float* row = g_P + ((size_t)(b*NH + h)*TGT + q)*TGT;
        float v[8];
        float mx = -1e30f;
        #pragma unroll
        for (int r=0;r<8;r++) { v[r] = row[tid + r*256]; mx = fmaxf(mx, v[r]); }
        #pragma unroll
        for (int o=16;o;o>>=1) mx = fmaxf(mx, __shfl_xor_sync(0xffffffffu, mx, o));
        if ((tid & 31) == 0) sred[tid >> 5] = mx;
        __syncthreads();
        if (tid < 32) {
            float x = (tid < 8) ? sred[tid] : -1e30f;
            #pragma unroll
            for (int o=4;o;o>>=1) x = fmaxf(x, __shfl_xor_sync(0xffffffffu, x, o));
            if (tid == 0) sred[0] = x;
        }
        __syncthreads();
        mx = sred[0];

        float sum = 0.f;
        #pragma unroll
        for (int r=0;r<8;r++) { v[r] = fast_exp(v[r] - mx); sum += v[r]; }
        #pragma unroll
        for (int o=16;o;o>>=1) sum += __shfl_xor_sync(0xffffffffu, sum, o);
        __syncthreads();                    // protect sred reuse
        if ((tid & 31) == 0) sred[tid >> 5] = sum;
        __syncthreads();
        if (tid < 32) {
            float x = (tid < 8) ? sred[tid] : 0.f;
            #pragma unroll
            for (int o=4;o;o>>=1) x += __shfl_xor_sync(0xffffffffu, x, o);
            if (tid == 0) sred[0] = x;
        }
        __syncthreads();
        const float inv = 1.0f / sred[0];

        #pragma unroll
        for (int r=0;r<8;r++) {
            const float p = v[r] * inv;
            row[tid + r*256] = p;
            s_avg[tid + r*256] += p;
        }
        __syncthreads();                    // before sred reuse next head
    }

    const float invH = 1.0f / NH;
    float* dst = avg_out + ((size_t)b*TGT + q)*TGT;
    #pragma unroll
    for (int r=0;r<TGT/256;r++) dst[tid + r*256] = s_avg[tid + r*256] * invH;
}

extern "C" void kernel_launch(void* const* d_in, const int* in_sizes, int n_in,
                              void* d_out, int out_size)
{
    const float* query = (const float*)d_in[0];   // [T,B,E]
    const float* w_in  = (const float*)d_in[1];   // [3E,E]
    const float* b_in  = (const float*)d_in[2];   // [3E]
    const float* w_out = (const float*)d_in[3];   // [E,E]
    const float* b_out = (const float*)d_in[4];   // [E]

    float* out      = (float*)d_out;
    float* attn_out = out;                                 // [T,B,E]
    float* avg_out  = out + (size_t)TGT*NBSZ*EMB;          // [B,T,T]

    // 1. QKV projection: [4096,1024] x [3072,1024]^T, scatter to heads
    gemm_k<128,128,8,8,0><<<dim3(3*EMB/128, MROWS/128, 1), 256>>>(
        query, w_in, nullptr, b_in, EMB);

    // 2. Scores: per bh, [2048,64] x [2048,64]^T -> g_P
    gemm_k<128,128,8,8,1><<<dim3(TGT/128, TGT/128, NBH), 256>>>(
        nullptr, nullptr, nullptr, nullptr, HD);

    // 3. Softmax rows + head-averaged weights
    softmax_avg_k<<<dim3(TGT, NBSZ), 256>>>(avg_out);

    // 4. PV: per bh, [2048,2048] x [64,2048]^T -> g_attn (reordered)
    gemm_k<128,64,8,4,2><<<dim3(1, TGT/128, NBH), 256>>>(
        nullptr, nullptr, nullptr, nullptr, TGT);

    // 5. Output projection: [4096,1024] x [1024,1024]^T + bias -> attn output
    gemm_k<128,128,8,8,3><<<dim3(EMB/128, MROWS/128, 1), 256>>>(
        nullptr, w_out, attn_out, b_out, EMB);
}

// round 3
// speedup vs baseline: 2.5382x; 2.5382x over previous
#include <cuda_runtime.h>
#include <cstdint>
#include <math.h>

#define TGT   2048
#define NBSZ  2
#define EMB   1024
#define NH    16
#define HD    64
#define NBH   (NBSZ*NH)      // 32
#define MROWS (TGT*NBSZ)     // 4096

// ---------------- scratch (device globals: allocation-free rule) -----------
static __device__ float g_Q  [(size_t)NBH*TGT*HD];   // [bh][t][d], pre-scaled
static __device__ float g_K  [(size_t)NBH*TGT*HD];   // [bh][t][d]
static __device__ float g_Vt [(size_t)NBH*HD*TGT];   // [bh][d][t]
static __device__ float g_P  [(size_t)NBH*TGT*TGT];  // logits -> probs
static __device__ float g_attn[(size_t)MROWS*EMB];   // pre-out-proj [t*B+b][e]

// ---------------- tf32 helpers ----------------------------------------------
__device__ __forceinline__ uint32_t f2tf32(float x){
    uint32_t u; asm("cvt.rna.tf32.f32 %0, %1;" : "=r"(u) : "f"(x)); return u;
}
__device__ __forceinline__ float4 tf4(float4 v){
    v.x = __uint_as_float(f2tf32(v.x));
    v.y = __uint_as_float(f2tf32(v.y));
    v.z = __uint_as_float(f2tf32(v.z));
    v.w = __uint_as_float(f2tf32(v.w));
    return v;
}
// m16n8k8 tf32 MMA (A row-major, B col-major k x n == B[n][k])
__device__ __forceinline__ void mma8(float* c, const uint32_t* a, const uint32_t* b){
    asm volatile("mma.sync.aligned.m16n8k8.row.col.f32.tf32.tf32.f32 "
        "{%0,%1,%2,%3}, {%4,%5,%6,%7}, {%8,%9}, {%0,%1,%2,%3};"
        : "+f"(c[0]), "+f"(c[1]), "+f"(c[2]), "+f"(c[3])
        : "r"(a[0]), "r"(a[1]), "r"(a[2]), "r"(a[3]), "r"(b[0]), "r"(b[1]));
}

// SMEM layout (floats): A bufs at 0 / 4608 (128 rows x stride 36),
//                       B bufs at 9216 / 11520 (64 rows x stride 36)
#define LDSROW 36
#define SM_A1  4608
#define SM_B   9216
#define SM_B1  2304
#define SMEM_FLOATS 13824
#define SMEM_BYTES  (SMEM_FLOATS*4)   // 55296

// ---------------------------------------------------------------------------
// HMMA tf32 GEMM: C[M,N] = A[M,K] * B[N,K]^T, block 128x64, BK=32, 128 thr.
// MODE 0: QKV  A=query[4096,1024] B=w_in[3072,1024] (+bias) -> scatter Q/K/Vt
// MODE 1: per-z bh: A=g_Q[2048,64]  B=g_K[2048,64]   -> g_P logits
// MODE 2: per-z bh: A=g_P[2048,2048] B=g_Vt[64,2048] -> g_attn (reordered)
// MODE 3: A=g_attn[4096,1024] B=w_out[1024,1024] (+bias) -> attn_out
// ---------------------------------------------------------------------------
template<int MODE>
__global__ __launch_bounds__(128)
void mma_gemm(const float* __restrict__ Ag, const float* __restrict__ Bg,
              float* __restrict__ Cg, const float* __restrict__ biasg)
{
    constexpr int Kd = (MODE==1) ? 64 : (MODE==2) ? 2048 : 1024;
    constexpr int KC = Kd / 32;

    extern __shared__ float sm[];
    const int tid = threadIdx.x, lane = tid & 31, wid = tid >> 5;
    const int wm = wid & 1, wn = wid >> 1;        // warp grid 2(m) x 2(n)
    const int lr = lane >> 2, lc = lane & 3;
    const int bx = blockIdx.x, by = blockIdx.y, z = blockIdx.z;
    const int bm = by * 128, bn = bx * 64;

    const float* A; const float* B; int lda, ldb;
    if (MODE == 0)      { A = Ag;                      B = Bg;                      lda = EMB; ldb = EMB; }
    else if (MODE == 1) { A = g_Q + (size_t)z*TGT*HD;  B = g_K  + (size_t)z*TGT*HD; lda = HD;  ldb = HD;  }
    else if (MODE == 2) { A = g_P + (size_t)z*TGT*TGT; B = g_Vt + (size_t)z*HD*TGT; lda = TGT; ldb = TGT; }
    else                { A = g_attn;                  B = Bg;                      lda = EMB; ldb = EMB; }

    float acc[4][4][4];
    #pragma unroll
    for (int i=0;i<4;i++)
        #pragma unroll
        for (int j=0;j<4;j++)
            #pragma unroll
            for (int k=0;k<4;k++) acc[i][j][k] = 0.f;

    float4 stA[8], stB[4];

    auto ldg_chunk = [&](int k0){
        #pragma unroll
        for (int t=0;t<8;t++){
            int fi = tid + t*128, r = fi>>3, c4 = fi&7;
            stA[t] = *(const float4*)(A + (size_t)(bm+r)*lda + k0 + c4*4);
        }
        #pragma unroll
        for (int t=0;t<4;t++){
            int fi = tid + t*128, r = fi>>3, c4 = fi&7;
            stB[t] = *(const float4*)(B + (size_t)(bn+r)*ldb + k0 + c4*4);
        }
    };
    auto sts_chunk = [&](int buf){
        float* a = sm + buf*SM_A1;
        float* b = sm + SM_B + buf*SM_B1;
        #pragma unroll
        for (int t=0;t<8;t++){
            int fi = tid + t*128, r = fi>>3, c4 = fi&7;
            *(float4*)(a + r*LDSROW + c4*4) = tf4(stA[t]);
        }
        #pragma unroll
        for (int t=0;t<4;t++){
            int fi = tid + t*128, r = fi>>3, c4 = fi&7;
            *(float4*)(b + r*LDSROW + c4*4) = tf4(stB[t]);
        }
    };

    ldg_chunk(0);
    sts_chunk(0);
    __syncthreads();

    for (int c = 0; c < KC; c++) {
        const int buf = c & 1;
        if (c + 1 < KC) ldg_chunk((c+1)*32);

        const float* Ab = sm + buf*SM_A1;
        const float* Bb = sm + SM_B + buf*SM_B1;
        #pragma unroll
        for (int ks = 0; ks < 4; ks++) {
            uint32_t af[4][4], bf[4][2];
            #pragma unroll
            for (int mt=0; mt<4; mt++){
                const float* p = Ab + (wm*64 + mt*16 + lr)*LDSROW + ks*8 + lc;
                af[mt][0] = __float_as_uint(p[0]);
                af[mt][1] = __float_as_uint(p[8*LDSROW]);
                af[mt][2] = __float_as_uint(p[4]);
                af[mt][3] = __float_as_uint(p[8*LDSROW + 4]);
            }
            #pragma unroll
            for (int nt=0; nt<4; nt++){
                const float* p = Bb + (wn*32 + nt*8 + lr)*LDSROW + ks*8 + lc;
                bf[nt][0] = __float_as_uint(p[0]);
                bf[nt][1] = __float_as_uint(p[4]);
            }
            #pragma unroll
            for (int mt=0; mt<4; mt++)
                #pragma unroll
                for (int nt=0; nt<4; nt++)
                    mma8(acc[mt][nt], af[mt], bf[nt]);
        }
        if (c + 1 < KC) {
            sts_chunk((c+1)&1);
            __syncthreads();
        }
    }

    // ---- epilogue ----
    float bias0[4], bias1[4];
    if (MODE == 0 || MODE == 3) {
        #pragma unroll
        for (int nt=0; nt<4; nt++){
            int n = bn + wn*32 + nt*8 + lc*2;
            bias0[nt] = biasg[n]; bias1[nt] = biasg[n+1];
        }
    }

    #pragma unroll
    for (int mt=0; mt<4; mt++)
    #pragma unroll
    for (int half=0; half<2; half++){
        const int m = bm + wm*64 + mt*16 + half*8 + lr;
        if (MODE == 0) {
            const int t = m >> 1, b = m & 1;
            #pragma unroll
            for (int nt=0; nt<4; nt++){
                const int n = bn + wn*32 + nt*8 + lc*2;
                float v0 = acc[mt][nt][half*2+0] + bias0[nt];
                float v1 = acc[mt][nt][half*2+1] + bias1[nt];
                const int which = n >> 10, e = n & 1023, h = e >> 6, d = e & 63;
                const int bh = b*NH + h;
                if (which == 0) {
                    float2 o = make_float2(v0*0.125f, v1*0.125f);
                    *(float2*)&g_Q[((size_t)bh*TGT + t)*HD + d] = o;
                } else if (which == 1) {
                    float2 o = make_float2(v0, v1);
                    *(float2*)&g_K[((size_t)bh*TGT + t)*HD + d] = o;
                } else {
                    g_Vt[((size_t)bh*HD + d    )*TGT + t] = v0;
                    g_Vt[((size_t)bh*HD + d + 1)*TGT + t] = v1;
                }
            }
        } else if (MODE == 1) {
            float* dst = g_P + (size_t)z*TGT*TGT + (size_t)m*TGT;
            #pragma unroll
            for (int nt=0; nt<4; nt++){
                const int n = bn + wn*32 + nt*8 + lc*2;
                *(float2*)&dst[n] = make_float2(acc[mt][nt][half*2], acc[mt][nt][half*2+1]);
            }
        } else if (MODE == 2) {
            const int b = z >> 4, h = z & 15;
            float* dst = g_attn + ((size_t)m*NBSZ + b)*EMB + h*HD;
            #pragma unroll
            for (int nt=0; nt<4; nt++){
                const int n = wn*32 + nt*8 + lc*2;
                *(float2*)&dst[n] = make_float2(acc[mt][nt][half*2], acc[mt][nt][half*2+1]);
            }
        } else {
            float* dst = Cg + (size_t)m*EMB;
            #pragma unroll
            for (int nt=0; nt<4; nt++){
                const int n = bn + wn*32 + nt*8 + lc*2;
                *(float2*)&dst[n] = make_float2(acc[mt][nt][half*2] + bias0[nt],
                                                acc[mt][nt][half*2+1] + bias1[nt]);
            }
        }
    }
}

// ---------------- FFMA-only exp --------------------------------------------
__device__ __forceinline__ float fast_exp(float x)
{
    float y = x * 1.4426950408889634f;
    float n = rintf(y);
    float t = y - n;
    float p =            1.33336498e-3f;
    p = fmaf(p, t, 9.61812910e-3f);
    p = fmaf(p, t, 5.55041087e-2f);
    p = fmaf(p, t, 2.40226507e-1f);
    p = fmaf(p, t, 6.93147182e-1f);
    p = fmaf(p, t, 1.0f);
    int e = (int)n;
    e = max(-126, min(126, e));
    return p * __int_as_float((e + 127) << 23);
}

// ---------------- softmax + head-average (validated round 1) ---------------
__global__ __launch_bounds__(256)
void softmax_avg_k(float* __restrict__ avg_out)
{
    const int q = blockIdx.x, b = blockIdx.y;
    const int tid = threadIdx.x;
    __shared__ float s_avg[TGT];
    __shared__ float sred[8];

    #pragma unroll
    for (int r = 0; r < TGT/256; r++) s_avg[tid + r*256] = 0.f;

    for (int h = 0; h < NH; h++) {
        float* row = g_P + ((size_t)(b*NH + h)*TGT + q)*TGT;
        float v[8];
        float mx = -1e30f;
        #pragma unroll
        for (int r = 0; r < 8; r++) { v[r] = row[tid + r*256]; mx = fmaxf(mx, v[r]); }
        #pragma unroll
        for (int o = 16; o; o >>= 1) mx = fmaxf(mx, __shfl_xor_sync(0xffffffffu, mx, o));
        if ((tid & 31) == 0) sred[tid >> 5] = mx;
        __syncthreads();
        if (tid < 32) {
            float x = (tid < 8) ? sred[tid] : -1e30f;
            #pragma unroll
            for (int o = 4; o; o >>= 1) x = fmaxf(x, __shfl_xor_sync(0xffffffffu, x, o));
            if (tid == 0) sred[0] = x;
        }
        __syncthreads();
        mx = sred[0];

        float sum = 0.f;
        #pragma unroll
        for (int r = 0; r < 8; r++) { v[r] = fast_exp(v[r] - mx); sum += v[r]; }
        #pragma unroll
        for (int o = 16; o; o >>= 1) sum += __shfl_xor_sync(0xffffffffu, sum, o);
        __syncthreads();
        if ((tid & 31) == 0) sred[tid >> 5] = sum;
        __syncthreads();
        if (tid < 32) {
            float x = (tid < 8) ? sred[tid] : 0.f;
            #pragma unroll
            for (int o = 4; o; o >>= 1) x += __shfl_xor_sync(0xffffffffu, x, o);
            if (tid == 0) sred[0] = x;
        }
        __syncthreads();
        const float inv = 1.0f / sred[0];

        #pragma unroll
        for (int r = 0; r < 8; r++) {
            const float p = v[r] * inv;
            row[tid + r*256] = p;
            s_avg[tid + r*256] += p;
        }
        __syncthreads();
    }

    const float invH = 1.0f / NH;
    float* dst = avg_out + ((size_t)b*TGT + q)*TGT;
    #pragma unroll
    for (int r = 0; r < TGT/256; r++) dst[tid + r*256] = s_avg[tid + r*256] * invH;
}

// ---------------------------------------------------------------------------
extern "C" void kernel_launch(void* const* d_in, const int* in_sizes, int n_in,
                              void* d_out, int out_size)
{
    const float* query = (const float*)d_in[0];   // [T,B,E]
    const float* w_in  = (const float*)d_in[1];   // [3E,E]
    const float* b_in  = (const float*)d_in[2];   // [3E]
    const float* w_out = (const float*)d_in[3];   // [E,E]
    const float* b_out = (const float*)d_in[4];   // [E]

    float* out      = (float*)d_out;
    float* attn_out = out;                                 // [T,B,E]
    float* avg_out  = out + (size_t)TGT*NBSZ*EMB;          // [B,T,T]

    cudaFuncSetAttribute(mma_gemm<0>, cudaFuncAttributeMaxDynamicSharedMemorySize, SMEM_BYTES);
    cudaFuncSetAttribute(mma_gemm<1>, cudaFuncAttributeMaxDynamicSharedMemorySize, SMEM_BYTES);
    cudaFuncSetAttribute(mma_gemm<2>, cudaFuncAttributeMaxDynamicSharedMemorySize, SMEM_BYTES);
    cudaFuncSetAttribute(mma_gemm<3>, cudaFuncAttributeMaxDynamicSharedMemorySize, SMEM_BYTES);

    // 1. QKV projection (tf32 HMMA)
    mma_gemm<0><<<dim3(3*EMB/64, MROWS/128), 128, SMEM_BYTES>>>(query, w_in, nullptr, b_in);

    // 2. Scores S = Q K^T per (b,h)
    mma_gemm<1><<<dim3(TGT/64, TGT/128, NBH), 128, SMEM_BYTES>>>(nullptr, nullptr, nullptr, nullptr);

    // 3. Softmax rows + head-averaged weights
    softmax_avg_k<<<dim3(TGT, NBSZ), 256>>>(avg_out);

    // 4. PV per (b,h)
    mma_gemm<2><<<dim3(1, TGT/128, NBH), 128, SMEM_BYTES>>>(nullptr, nullptr, nullptr, nullptr);

    // 5. Output projection
    mma_gemm<3><<<dim3(EMB/64, MROWS/128), 128, SMEM_BYTES>>>(nullptr, w_out, attn_out, b_out);
}

// round 4
// speedup vs baseline: 2.8672x; 1.1296x over previous
#include <cuda_runtime.h>
#include <cstdint>
#include <math.h>

#define TGT   2048
#define NBSZ  2
#define EMB   1024
#define NH    16
#define HD    64
#define NBH   (NBSZ*NH)      // 32
#define MROWS (TGT*NBSZ)     // 4096

// ---------------- scratch (device globals: allocation-free rule) -----------
static __device__ float  g_Q  [(size_t)NBH*TGT*HD];   // [bh][t][d], pre-scaled
static __device__ float  g_K  [(size_t)NBH*TGT*HD];   // [bh][t][d]
static __device__ float  g_Vt [(size_t)NBH*HD*TGT];   // [bh][d][t]
static __device__ float  g_attn[(size_t)MROWS*EMB];   // pre-out-proj [t*B+b][e]
static __device__ float2 g_stats[(size_t)NBH*TGT];    // (rowmax, 1/rowsum)

// ---------------- tf32 helpers ----------------------------------------------
__device__ __forceinline__ uint32_t f2tf32(float x){
    uint32_t u; asm("cvt.rna.tf32.f32 %0, %1;" : "=r"(u) : "f"(x)); return u;
}
__device__ __forceinline__ float4 tf4(float4 v){
    v.x = __uint_as_float(f2tf32(v.x));
    v.y = __uint_as_float(f2tf32(v.y));
    v.z = __uint_as_float(f2tf32(v.z));
    v.w = __uint_as_float(f2tf32(v.w));
    return v;
}
__device__ __forceinline__ void mma8(float* c, const uint32_t* a, const uint32_t* b){
    asm volatile("mma.sync.aligned.m16n8k8.row.col.f32.tf32.tf32.f32 "
        "{%0,%1,%2,%3}, {%4,%5,%6,%7}, {%8,%9}, {%0,%1,%2,%3};"
        : "+f"(c[0]), "+f"(c[1]), "+f"(c[2]), "+f"(c[3])
        : "r"(a[0]), "r"(a[1]), "r"(a[2]), "r"(a[3]), "r"(b[0]), "r"(b[1]));
}

// ===========================================================================
// Projection GEMMs (validated round 3): C[M,N] = A[M,K] * B[N,K]^T
// MODE 0: QKV, MODE 3: out-proj
// ===========================================================================
#define LDSROW 36
#define SM_A1  4608
#define SM_B   9216
#define SM_B1  2304
#define GEMM_SMEM_BYTES (13824*4)

template<int MODE>
__global__ __launch_bounds__(128)
void mma_gemm(const float* __restrict__ Ag, const float* __restrict__ Bg,
              float* __restrict__ Cg, const float* __restrict__ biasg)
{
    constexpr int Kd = 1024;
    constexpr int KC = Kd / 32;

    extern __shared__ float sm[];
    const int tid = threadIdx.x, lane = tid & 31, wid = tid >> 5;
    const int wm = wid & 1, wn = wid >> 1;
    const int lr = lane >> 2, lc = lane & 3;
    const int bx = blockIdx.x, by = blockIdx.y;
    const int bm = by * 128, bn = bx * 64;

    const float* A = (MODE == 0) ? Ag : g_attn;
    const float* B = Bg;
    const int lda = EMB, ldb = EMB;

    float acc[4][4][4];
    #pragma unroll
    for (int i=0;i<4;i++) for (int j=0;j<4;j++) for (int k=0;k<4;k++) acc[i][j][k]=0.f;

    float4 stA[8], stB[4];
    auto ldg_chunk = [&](int k0){
        #pragma unroll
        for (int t=0;t<8;t++){
            int fi = tid + t*128, r = fi>>3, c4 = fi&7;
            stA[t] = *(const float4*)(A + (size_t)(bm+r)*lda + k0 + c4*4);
        }
        #pragma unroll
        for (int t=0;t<4;t++){
            int fi = tid + t*128, r = fi>>3, c4 = fi&7;
            stB[t] = *(const float4*)(B + (size_t)(bn+r)*ldb + k0 + c4*4);
        }
    };
    auto sts_chunk = [&](int buf){
        float* a = sm + buf*SM_A1;
        float* b = sm + SM_B + buf*SM_B1;
        #pragma unroll
        for (int t=0;t<8;t++){
            int fi = tid + t*128, r = fi>>3, c4 = fi&7;
            *(float4*)(a + r*LDSROW + c4*4) = tf4(stA[t]);
        }
        #pragma unroll
        for (int t=0;t<4;t++){
            int fi = tid + t*128, r = fi>>3, c4 = fi&7;
            *(float4*)(b + r*LDSROW + c4*4) = tf4(stB[t]);
        }
    };

    ldg_chunk(0); sts_chunk(0); __syncthreads();

    for (int c = 0; c < KC; c++) {
        const int buf = c & 1;
        if (c + 1 < KC) ldg_chunk((c+1)*32);
        const float* Ab = sm + buf*SM_A1;
        const float* Bb = sm + SM_B + buf*SM_B1;
        #pragma unroll
        for (int ks = 0; ks < 4; ks++) {
            uint32_t af[4][4], bf[4][2];
            #pragma unroll
            for (int mt=0; mt<4; mt++){
                const float* p = Ab + (wm*64 + mt*16 + lr)*LDSROW + ks*8 + lc;
                af[mt][0]=__float_as_uint(p[0]); af[mt][1]=__float_as_uint(p[8*LDSROW]);
                af[mt][2]=__float_as_uint(p[4]); af[mt][3]=__float_as_uint(p[8*LDSROW+4]);
            }
            #pragma unroll
            for (int nt=0; nt<4; nt++){
                const float* p = Bb + (wn*32 + nt*8 + lr)*LDSROW + ks*8 + lc;
                bf[nt][0]=__float_as_uint(p[0]); bf[nt][1]=__float_as_uint(p[4]);
            }
            #pragma unroll
            for (int mt=0; mt<4; mt++)
                #pragma unroll
                for (int nt=0; nt<4; nt++)
                    mma8(acc[mt][nt], af[mt], bf[nt]);
        }
        if (c + 1 < KC) { sts_chunk((c+1)&1); __syncthreads(); }
    }

    float bias0[4], bias1[4];
    #pragma unroll
    for (int nt=0; nt<4; nt++){
        int n = bn + wn*32 + nt*8 + lc*2;
        bias0[nt] = biasg[n]; bias1[nt] = biasg[n+1];
    }

    #pragma unroll
    for (int mt=0; mt<4; mt++)
    #pragma unroll
    for (int half=0; half<2; half++){
        const int m = bm + wm*64 + mt*16 + half*8 + lr;
        if (MODE == 0) {
            const int t = m >> 1, b = m & 1;
            #pragma unroll
            for (int nt=0; nt<4; nt++){
                const int n = bn + wn*32 + nt*8 + lc*2;
                float v0 = acc[mt][nt][half*2+0] + bias0[nt];
                float v1 = acc[mt][nt][half*2+1] + bias1[nt];
                const int which = n >> 10, e = n & 1023, h = e >> 6, d = e & 63;
                const int bh = b*NH + h;
                if (which == 0) {
                    *(float2*)&g_Q[((size_t)bh*TGT + t)*HD + d] = make_float2(v0*0.125f, v1*0.125f);
                } else if (which == 1) {
                    *(float2*)&g_K[((size_t)bh*TGT + t)*HD + d] = make_float2(v0, v1);
                } else {
                    g_Vt[((size_t)bh*HD + d    )*TGT + t] = v0;
                    g_Vt[((size_t)bh*HD + d + 1)*TGT + t] = v1;
                }
            }
        } else {
            float* dst = Cg + (size_t)m*EMB;
            #pragma unroll
            for (int nt=0; nt<4; nt++){
                const int n = bn + wn*32 + nt*8 + lc*2;
                *(float2*)&dst[n] = make_float2(acc[mt][nt][half*2] + bias0[nt],
                                                acc[mt][nt][half*2+1] + bias1[nt]);
            }
        }
    }
}

// ===========================================================================
// Flash attention: per (b,h,q-tile 128). Online softmax, no P in DRAM.
// SMEM floats: QB[2][128][36] @0, KB[2][64][36] @9216, VB[2][64][36] @13824,
//              PB[2][128][36] @18432. Total 27648 floats = 110592 B.
// ===========================================================================
#define FA_SMEM_BYTES (27648*4)

__global__ __launch_bounds__(128)
void flash_attn_k()
{
    extern __shared__ float sm[];
    const int tid = threadIdx.x, lane = tid & 31, w = tid >> 5;
    const int lr = lane >> 2, lc = lane & 3;
    const int qt = blockIdx.x, bh = blockIdx.y;
    const int b = bh >> 4, h = bh & 15;
    const int qbase = qt * 128;

    const float* Qg = g_Q  + (size_t)bh*TGT*HD;
    const float* Kg = g_K  + (size_t)bh*TGT*HD;
    const float* Vg = g_Vt + (size_t)bh*HD*TGT;

    float* QB = sm;
    float* KB = sm + 9216;
    float* VB = sm + 13824;
    float* PB = sm + 18432;

    // Q tile once (tf32)
    #pragma unroll
    for (int i=0;i<16;i++){
        int fi = tid + i*128, r = fi>>4, c4 = fi&15;
        float4 v = tf4(*(const float4*)(Qg + (size_t)(qbase+r)*HD + c4*4));
        *(float4*)(QB + (c4>=8)*4608 + r*36 + (c4&7)*4) = v;
    }

    float acc_o[2][8][4];
    #pragma unroll
    for (int i=0;i<2;i++) for (int j=0;j<8;j++) for (int k=0;k<4;k++) acc_o[i][j][k]=0.f;
    float m_r[2][2] = {{-1e30f,-1e30f},{-1e30f,-1e30f}};
    float l_r[2][2] = {{0.f,0.f},{0.f,0.f}};

    for (int kc = 0; kc < TGT/64; kc++) {
        // K,V chunk (tf32)
        #pragma unroll
        for (int i=0;i<8;i++){
            int fi = tid + i*128, r = fi>>4, c4 = fi&15;
            float4 v = tf4(*(const float4*)(Kg + (size_t)(kc*64+r)*HD + c4*4));
            *(float4*)(KB + (c4>=8)*2304 + r*36 + (c4&7)*4) = v;
        }
        #pragma unroll
        for (int i=0;i<8;i++){
            int fi = tid + i*128, d = fi>>4, c4 = fi&15;
            float4 v = tf4(*(const float4*)(Vg + (size_t)d*TGT + kc*64 + c4*4));
            *(float4*)(VB + (c4>=8)*2304 + d*36 + (c4&7)*4) = v;
        }
        __syncthreads();

        // S = Q K^T  (128 x 64)
        float s[2][8][4];
        #pragma unroll
        for (int i=0;i<2;i++) for (int j=0;j<8;j++) for (int k=0;k<4;k++) s[i][j][k]=0.f;
        #pragma unroll
        for (int ks=0; ks<8; ks++){
            const int hb = ks>>2, ko = (ks&3)*8;
            uint32_t af[2][4], bf[8][2];
            #pragma unroll
            for (int mt=0; mt<2; mt++){
                const float* p = QB + hb*4608 + (w*32 + mt*16 + lr)*36 + ko + lc;
                af[mt][0]=__float_as_uint(p[0]); af[mt][1]=__float_as_uint(p[8*36]);
                af[mt][2]=__float_as_uint(p[4]); af[mt][3]=__float_as_uint(p[8*36+4]);
            }
            #pragma unroll
            for (int nt=0; nt<8; nt++){
                const float* p = KB + hb*2304 + (nt*8 + lr)*36 + ko + lc;
                bf[nt][0]=__float_as_uint(p[0]); bf[nt][1]=__float_as_uint(p[4]);
            }
            #pragma unroll
            for (int mt=0; mt<2; mt++)
                #pragma unroll
                for (int nt=0; nt<8; nt++)
                    mma8(s[mt][nt], af[mt], bf[nt]);
        }

        // online softmax update
        #pragma unroll
        for (int mt=0; mt<2; mt++)
        #pragma unroll
        for (int hf=0; hf<2; hf++){
            float cm = -1e30f;
            #pragma unroll
            for (int nt=0; nt<8; nt++)
                cm = fmaxf(cm, fmaxf(s[mt][nt][hf*2], s[mt][nt][hf*2+1]));
            cm = fmaxf(cm, __shfl_xor_sync(0xffffffffu, cm, 1));
            cm = fmaxf(cm, __shfl_xor_sync(0xffffffffu, cm, 2));
            const float mn = fmaxf(m_r[mt][hf], cm);
            const float sc = __expf(m_r[mt][hf] - mn);
            float cs = 0.f;
            #pragma unroll
            for (int nt=0; nt<8; nt++){
                float e0 = __expf(s[mt][nt][hf*2]   - mn);
                float e1 = __expf(s[mt][nt][hf*2+1] - mn);
                s[mt][nt][hf*2]   = e0;
                s[mt][nt][hf*2+1] = e1;
                cs += e0 + e1;
            }
            cs += __shfl_xor_sync(0xffffffffu, cs, 1);
            cs += __shfl_xor_sync(0xffffffffu, cs, 2);
            l_r[mt][hf] = l_r[mt][hf]*sc + cs;
            m_r[mt][hf] = mn;
            #pragma unroll
            for (int nt=0; nt<8; nt++){
                acc_o[mt][nt][hf*2]   *= sc;
                acc_o[mt][nt][hf*2+1] *= sc;
            }
        }

        // P -> smem (tf32, warp-private rows)
        #pragma unroll
        for (int mt=0; mt<2; mt++)
        #pragma unroll
        for (int nt=0; nt<8; nt++)
        #pragma unroll
        for (int hf=0; hf<2; hf++){
            const int row = w*32 + mt*16 + hf*8 + lr;
            float2 pv;
            pv.x = __uint_as_float(f2tf32(s[mt][nt][hf*2]));
            pv.y = __uint_as_float(f2tf32(s[mt][nt][hf*2+1]));
            *(float2*)(PB + (nt>>2)*4608 + row*36 + (nt&3)*8 + lc*2) = pv;
        }
        __syncwarp();

        // O += P V   (k dim = 64 chunk cols)
        #pragma unroll
        for (int ks=0; ks<8; ks++){
            const int hb = ks>>2, ko = (ks&3)*8;
            uint32_t af[2][4], bf[8][2];
            #pragma unroll
            for (int mt=0; mt<2; mt++){
                const float* p = PB + hb*4608 + (w*32 + mt*16 + lr)*36 + ko + lc;
                af[mt][0]=__float_as_uint(p[0]); af[mt][1]=__float_as_uint(p[8*36]);
                af[mt][2]=__float_as_uint(p[4]); af[mt][3]=__float_as_uint(p[8*36+4]);
            }
            #pragma unroll
            for (int nt=0; nt<8; nt++){
                const float* p = VB + hb*2304 + (nt*8 + lr)*36 + ko + lc;
                bf[nt][0]=__float_as_uint(p[0]); bf[nt][1]=__float_as_uint(p[4]);
            }
            #pragma unroll
            for (int mt=0; mt<2; mt++)
                #pragma unroll
                for (int nt=0; nt<8; nt++)
                    mma8(acc_o[mt][nt], af[mt], bf[nt]);
        }
        __syncthreads();
    }

    // epilogue: normalize, write O and stats
    #pragma unroll
    for (int mt=0; mt<2; mt++)
    #pragma unroll
    for (int hf=0; hf<2; hf++){
        const float invl = 1.0f / l_r[mt][hf];
        const int q = qbase + w*32 + mt*16 + hf*8 + lr;
        float* dst = g_attn + ((size_t)q*NBSZ + b)*EMB + h*HD;
        #pragma unroll
        for (int nt=0; nt<8; nt++){
            *(float2*)(dst + nt*8 + lc*2) =
                make_float2(acc_o[mt][nt][hf*2]*invl, acc_o[mt][nt][hf*2+1]*invl);
        }
        if (lc == 0)
            g_stats[(size_t)bh*TGT + q] = make_float2(m_r[mt][hf], invl);
    }
}

// ===========================================================================
// avg weights: per (k-tile 64, q-tile 128, b). Recomputes S per head,
// applies stored stats, accumulates mean over heads. No P storage.
// SMEM: QB[2][128][36] @0, KB[2][64][36] @9216 -> 13824 floats = 55296 B.
// ===========================================================================
#define AVG_SMEM_BYTES (13824*4)

__global__ __launch_bounds__(128)
void avg_attn_k(float* __restrict__ avg_out)
{
    extern __shared__ float sm[];
    float* QB = sm;
    float* KB = sm + 9216;
    const int tid = threadIdx.x, lane = tid & 31, w = tid >> 5;
    const int lr = lane >> 2, lc = lane & 3;
    const int kt = blockIdx.x, qt = blockIdx.y, b = blockIdx.z;

    float acc[2][8][4];
    #pragma unroll
    for (int i=0;i<2;i++) for (int j=0;j<8;j++) for (int k=0;k<4;k++) acc[i][j][k]=0.f;

    for (int h = 0; h < NH; h++) {
        const int bh = b*NH + h;
        const float* Qg = g_Q + (size_t)bh*TGT*HD;
        const float* Kg = g_K + (size_t)bh*TGT*HD;
        #pragma unroll
        for (int i=0;i<16;i++){
            int fi = tid + i*128, r = fi>>4, c4 = fi&15;
            float4 v = tf4(*(const float4*)(Qg + (size_t)(qt*128+r)*HD + c4*4));
            *(float4*)(QB + (c4>=8)*4608 + r*36 + (c4&7)*4) = v;
        }
        #pragma unroll
        for (int i=0;i<8;i++){
            int fi = tid + i*128, r = fi>>4, c4 = fi&15;
            float4 v = tf4(*(const float4*)(Kg + (size_t)(kt*64+r)*HD + c4*4));
            *(float4*)(KB + (c4>=8)*2304 + r*36 + (c4&7)*4) = v;
        }
        __syncthreads();

        float s[2][8][4];
        #pragma unroll
        for (int i=0;i<2;i++) for (int j=0;j<8;j++) for (int k=0;k<4;k++) s[i][j][k]=0.f;
        #pragma unroll
        for (int ks=0; ks<8; ks++){
            const int hb = ks>>2, ko = (ks&3)*8;
            uint32_t af[2][4], bf[8][2];
            #pragma unroll
            for (int mt=0; mt<2; mt++){
                const float* p = QB + hb*4608 + (w*32 + mt*16 + lr)*36 + ko + lc;
                af[mt][0]=__float_as_uint(p[0]); af[mt][1]=__float_as_uint(p[8*36]);
                af[mt][2]=__float_as_uint(p[4]); af[mt][3]=__float_as_uint(p[8*36+4]);
            }
            #pragma unroll
            for (int nt=0; nt<8; nt++){
                const float* p = KB + hb*2304 + (nt*8 + lr)*36 + ko + lc;
                bf[nt][0]=__float_as_uint(p[0]); bf[nt][1]=__float_as_uint(p[4]);
            }
            #pragma unroll
            for (int mt=0; mt<2; mt++)
                #pragma unroll
                for (int nt=0; nt<8; nt++)
                    mma8(s[mt][nt], af[mt], bf[nt]);
        }

        #pragma unroll
        for (int mt=0; mt<2; mt++)
        #pragma unroll
        for (int hf=0; hf<2; hf++){
            const int q = qt*128 + w*32 + mt*16 + hf*8 + lr;
            const float2 st = g_stats[(size_t)bh*TGT + q];
            #pragma unroll
            for (int nt=0; nt<8; nt++){
                acc[mt][nt][hf*2]   += __expf(s[mt][nt][hf*2]   - st.x) * st.y;
                acc[mt][nt][hf*2+1] += __expf(s[mt][nt][hf*2+1] - st.x) * st.y;
            }
        }
        __syncthreads();
    }

    const float invH = 1.0f / NH;
    #pragma unroll
    for (int mt=0; mt<2; mt++)
    #pragma unroll
    for (int hf=0; hf<2; hf++){
        const int q = qt*128 + w*32 + mt*16 + hf*8 + lr;
        float* dst = avg_out + ((size_t)b*TGT + q)*TGT + kt*64;
        #pragma unroll
        for (int nt=0; nt<8; nt++)
            *(float2*)(dst + nt*8 + lc*2) =
                make_float2(acc[mt][nt][hf*2]*invH, acc[mt][nt][hf*2+1]*invH);
    }
}

// ---------------------------------------------------------------------------
extern "C" void kernel_launch(void* const* d_in, const int* in_sizes, int n_in,
                              void* d_out, int out_size)
{
    const float* query = (const float*)d_in[0];
    const float* w_in  = (const float*)d_in[1];
    const float* b_in  = (const float*)d_in[2];
    const float* w_out = (const float*)d_in[3];
    const float* b_out = (const float*)d_in[4];

    float* out      = (float*)d_out;
    float* attn_out = out;                           // [T,B,E]
    float* avg_out  = out + (size_t)TGT*NBSZ*EMB;    // [B,T,T]

    cudaFuncSetAttribute(mma_gemm<0>,  cudaFuncAttributeMaxDynamicSharedMemorySize, GEMM_SMEM_BYTES);
    cudaFuncSetAttribute(mma_gemm<3>,  cudaFuncAttributeMaxDynamicSharedMemorySize, GEMM_SMEM_BYTES);
    cudaFuncSetAttribute(flash_attn_k, cudaFuncAttributeMaxDynamicSharedMemorySize, FA_SMEM_BYTES);
    cudaFuncSetAttribute(avg_attn_k,   cudaFuncAttributeMaxDynamicSharedMemorySize, AVG_SMEM_BYTES);

    // 1. QKV projection
    mma_gemm<0><<<dim3(3*EMB/64, MROWS/128), 128, GEMM_SMEM_BYTES>>>(query, w_in, nullptr, b_in);

    // 2. Flash attention (scores + softmax + PV fused), writes stats
    flash_attn_k<<<dim3(TGT/128, NBH), 128, FA_SMEM_BYTES>>>();

    // 3. Averaged attention weights (recompute S, use stats)
    avg_attn_k<<<dim3(TGT/64, TGT/128, NBSZ), 128, AVG_SMEM_BYTES>>>(avg_out);

    // 4. Output projection
    mma_gemm<3><<<dim3(EMB/64, MROWS/128), 128, GEMM_SMEM_BYTES>>>(nullptr, w_out, attn_out, b_out);
}